// round 5
// baseline (speedup 1.0000x reference)
#include <cuda_runtime.h>
#include <cuda.h>
#include <cstdint>

// ============================================================================
// GraphConvolution: out = adj[16384,16384] @ (x[16384,64] @ W[64,64]) + bias
//
// Round 5 = Round 4 (K-split x4, 16 compute warps) with two fixes:
//  (1) bar.sync across all compute threads BEFORE partial writes into the
//      drained tile region (fixes read-after-reuse race; round-4 7.9e-2).
//  (2) cvt.rna restored on A fragments (isolate precision change from race).
// ============================================================================

#define N_ROWS 16384
#define K_DIM  16384
#define IN_F   64
#define OUT_F  64

#define TILE_M 128
#define TILE_K 32                       // 32 fp32 = 128 B = SW128 atom row
#define STAGES 8
#define N_ITERS (K_DIM / TILE_K)        // 512

#define ADJ_TILE_BYTES (TILE_M * 128)   // 16384
#define B_TILE_BYTES   (OUT_F * 128)    // 8192
#define STAGE_BYTES    (ADJ_TILE_BYTES + B_TILE_BYTES)  // 24576

#define OFF_BARS  0                     // per stage: full @ 16*s, empty @ 16*s+8
#define OFF_TILES 1024
#define SMEM_BYTES (OFF_TILES + STAGES * STAGE_BYTES)   // 197632

#define N_CWARPS 16
#define PART_STRIDE 66                  // padded row stride (floats)
#define PART_ELEMS (TILE_M * PART_STRIDE)

// ---------------------------------------------------------------- PTX helpers
__device__ __forceinline__ uint32_t smem_to_u32(const void* p) {
    uint32_t a;
    asm("{ .reg .u64 t; cvta.to.shared.u64 t, %1; cvt.u32.u64 %0, t; }" : "=r"(a) : "l"(p));
    return a;
}

#define MBARRIER_INIT(addr, count) \
    asm volatile("mbarrier.init.shared.b64 [%0], %1;" :: "r"((uint32_t)(addr)), "r"((uint32_t)(count)) : "memory")

#define MBARRIER_ARRIVE(addr) \
    asm volatile("mbarrier.arrive.shared.b64 _, [%0];" :: "r"((uint32_t)(addr)) : "memory")

#define MBARRIER_EXPECT_TX(addr, bytes) \
    asm volatile("mbarrier.arrive.expect_tx.shared.b64 _, [%0], %1;" :: "r"((uint32_t)(addr)), "r"((uint32_t)(bytes)) : "memory")

#define MBARRIER_WAIT_PARITY(addr, parity) do {                                      \
    uint32_t _mbar = (uint32_t)(addr);                                               \
    uint32_t _par  = (uint32_t)(parity);                                             \
    uint32_t _done;                                                                  \
    asm volatile(                                                                    \
        "{\n\t.reg .pred p;\n\t"                                                     \
        "mbarrier.try_wait.parity.acquire.cta.shared::cta.b64 p, [%1], %2;\n\t"      \
        "selp.b32 %0, 1, 0, p;\n\t}"                                                 \
        : "=r"(_done) : "r"(_mbar), "r"(_par) : "memory");                           \
    if (!_done) {                                                                    \
        asm volatile(                                                                \
            "{\n\t.reg .pred P1;\n\t"                                                \
            "WAIT_LOOP_%=:\n\t"                                                      \
            "mbarrier.try_wait.parity.acquire.cta.shared::cta.b64 P1, [%0], %1, 0x989680;\n\t" \
            "@P1 bra.uni WAIT_DONE_%=;\n\t"                                          \
            "bra.uni WAIT_LOOP_%=;\n\t"                                              \
            "WAIT_DONE_%=:\n\t}"                                                     \
            :: "r"(_mbar), "r"(_par) : "memory");                                    \
    }                                                                                \
} while (0)

__device__ __forceinline__ void tma_load_2d_g(uint32_t smem_addr, const CUtensorMap* map,
                                              int cx, int cy, uint32_t mbar) {
    asm volatile(
        "cp.async.bulk.tensor.2d.shared::cta.global.tile.mbarrier::complete_tx::bytes "
        "[%0], [%1, {%2, %3}], [%4];"
        :: "r"(smem_addr), "l"(map), "r"(cx), "r"(cy), "r"(mbar) : "memory");
}

__device__ __forceinline__ uint32_t lds32(uint32_t a) {
    uint32_t v;
    asm volatile("ld.shared.b32 %0, [%1];" : "=r"(v) : "r"(a));
    return v;
}

__device__ __forceinline__ uint32_t f2tf32(uint32_t bits) {
    uint32_t o;
    asm("cvt.rna.tf32.f32 %0, %1;" : "=r"(o) : "f"(__uint_as_float(bits)));
    return o;
}

__device__ __forceinline__ void mma_tf32(float* c,
                                         uint32_t a0, uint32_t a1, uint32_t a2, uint32_t a3,
                                         uint32_t b0, uint32_t b1) {
    asm volatile(
        "mma.sync.aligned.m16n8k8.row.col.f32.tf32.tf32.f32 "
        "{%0,%1,%2,%3}, {%4,%5,%6,%7}, {%8,%9}, {%0,%1,%2,%3};"
        : "+f"(c[0]), "+f"(c[1]), "+f"(c[2]), "+f"(c[3])
        : "r"(a0), "r"(a1), "r"(a2), "r"(a3), "r"(b0), "r"(b1));
}

// ---------------------------------------------------------------- scratch
__device__ __align__(1024) float g_supT[(size_t)OUT_F * K_DIM];  // 4 MiB

// ---------------------------------------------------------------- kernel 1
__global__ void __launch_bounds__(256) gcn_support_kernel(const float* __restrict__ x,
                                                          const float* __restrict__ w,
                                                          float* __restrict__ supT) {
    __shared__ float ws[IN_F * OUT_F];
    int tid = threadIdx.x;
    for (int i = tid; i < IN_F * OUT_F; i += 256) ws[i] = w[i];
    __syncthreads();

    int k  = blockIdx.x * 64 + (tid & 63);
    int n0 = (tid >> 6) * (OUT_F / 4);

    float xr[IN_F];
    const float4* xv = reinterpret_cast<const float4*>(x + (size_t)k * IN_F);
#pragma unroll
    for (int i = 0; i < IN_F / 4; i++) {
        float4 v = xv[i];
        xr[4 * i] = v.x; xr[4 * i + 1] = v.y; xr[4 * i + 2] = v.z; xr[4 * i + 3] = v.w;
    }
#pragma unroll 4
    for (int nn = 0; nn < OUT_F / 4; nn++) {
        int n = n0 + nn;
        float acc = 0.f;
#pragma unroll
        for (int i = 0; i < IN_F; i++) acc = fmaf(xr[i], ws[i * OUT_F + n], acc);
        uint32_t t;
        asm("cvt.rna.tf32.f32 %0, %1;" : "=r"(t) : "f"(acc));  // pre-round to tf32
        supT[(size_t)n * K_DIM + k] = __uint_as_float(t);
    }
}

// ---------------------------------------------------------------- kernel 2
// 17 warps: wid 0..15 compute (4 row groups x 4 k-groups), wid 16 = producer.
__global__ void __launch_bounds__(544, 1) gcn_gemm_kernel(
    const __grid_constant__ CUtensorMap madj,
    const __grid_constant__ CUtensorMap msup,
    float* __restrict__ out,
    const float* __restrict__ bias)
{
    extern __shared__ char smem[];
    uint32_t sb = smem_to_u32(smem);
    int tid = threadIdx.x;
    int wid = tid >> 5;
    int lid = tid & 31;
    int m0 = blockIdx.x * TILE_M;

    if (tid == 0) {
        for (int s = 0; s < STAGES; s++) {
            MBARRIER_INIT(sb + OFF_BARS + s * 16, 1);            // full: 1 expect_tx
            MBARRIER_INIT(sb + OFF_BARS + s * 16 + 8, N_CWARPS); // empty: 16 arrives
        }
    }
    __syncthreads();

    if (wid == 16) {
        if (lid == 0) {
            // -------- producer: TMA loads, backpressured by empty barriers
            int s = 0; uint32_t ph = 1;  // flipped phase: first STAGES waits pass
            for (int it = 0; it < N_ITERS; it++) {
                uint32_t fb = sb + OFF_BARS + s * 16;
                MBARRIER_WAIT_PARITY(fb + 8, ph);
                MBARRIER_EXPECT_TX(fb, STAGE_BYTES);
                uint32_t a_sm = sb + OFF_TILES + s * STAGE_BYTES;
                tma_load_2d_g(a_sm,                  &madj, it * TILE_K, m0, fb);
                tma_load_2d_g(a_sm + ADJ_TILE_BYTES, &msup, it * TILE_K, 0,  fb);
                if (++s == STAGES) { s = 0; ph ^= 1; }
            }
        }
        return;
    }

    // -------- compute warps
    int cwid   = wid & 3;      // row group: rows [32*cwid, 32*cwid+32)
    int kgroup = wid >> 2;     // ks index 0..3 within each 32-wide k-tile
    int g = lid >> 2;          // 0..7
    int t = lid & 3;           // 0..3
    uint32_t xorv = (uint32_t)g << 4;   // SW128 swizzle term (rows used == g mod 8)

    uint32_t rA0 = (uint32_t)(cwid * 32 + g) * 128;   // mt0 upper 8 rows
    uint32_t rB[8];
#pragma unroll
    for (int nt = 0; nt < 8; nt++) rB[nt] = (uint32_t)(nt * 8 + g) * 128;

    float acc[2][8][4];
#pragma unroll
    for (int mt = 0; mt < 2; mt++)
#pragma unroll
        for (int nt = 0; nt < 8; nt++)
#pragma unroll
            for (int c = 0; c < 4; c++) acc[mt][nt][c] = 0.f;

    // column byte offsets for this warp's ks (constant across k-tiles)
    uint32_t cb0 = ((uint32_t)(kgroup * 32 + t * 4)) ^ xorv;        // col t
    uint32_t cb1 = ((uint32_t)(kgroup * 32 + t * 4 + 16)) ^ xorv;   // col t+4

    int s = 0; uint32_t ph = 0;
    for (int it = 0; it < N_ITERS; it++) {
        uint32_t fb = sb + OFF_BARS + s * 16;
        MBARRIER_WAIT_PARITY(fb, ph);
        uint32_t sA = sb + OFF_TILES + s * STAGE_BYTES;
        uint32_t sB = sA + ADJ_TILE_BYTES;

        uint32_t a00 = f2tf32(lds32(sA + rA0 + cb0));
        uint32_t a01 = f2tf32(lds32(sA + rA0 + 1024 + cb0));
        uint32_t a02 = f2tf32(lds32(sA + rA0 + cb1));
        uint32_t a03 = f2tf32(lds32(sA + rA0 + 1024 + cb1));
        uint32_t a10 = f2tf32(lds32(sA + rA0 + 2048 + cb0));
        uint32_t a11 = f2tf32(lds32(sA + rA0 + 3072 + cb0));
        uint32_t a12 = f2tf32(lds32(sA + rA0 + 2048 + cb1));
        uint32_t a13 = f2tf32(lds32(sA + rA0 + 3072 + cb1));

#pragma unroll
        for (int nt = 0; nt < 8; nt++) {
            uint32_t b0 = lds32(sB + rB[nt] + cb0);
            uint32_t b1 = lds32(sB + rB[nt] + cb1);
            mma_tf32(acc[0][nt], a00, a01, a02, a03, b0, b1);
            mma_tf32(acc[1][nt], a10, a11, a12, a13, b0, b1);
        }
        if (lid == 0) MBARRIER_ARRIVE(fb + 8);
        if (++s == STAGES) { s = 0; ph ^= 1; }
    }

    // -------- drain barrier: ALL compute warps must finish reading tile smem
    // before it is reused for partials (producer is provably done too: its
    // last load required all-warp empty arrivals for that slot).
    asm volatile("bar.sync 1, 512;" ::: "memory");

    // -------- reduction: kgroups 1..3 write partials to smem, kgroup 0 sums
    float* part = reinterpret_cast<float*>(smem + OFF_TILES);
    if (kgroup != 0) {
        float* pb = part + (size_t)(kgroup - 1) * PART_ELEMS;
#pragma unroll
        for (int mt = 0; mt < 2; mt++) {
            int r0 = cwid * 32 + mt * 16 + g;
#pragma unroll
            for (int nt = 0; nt < 8; nt++) {
                int col = nt * 8 + 2 * t;
                *reinterpret_cast<float2*>(pb + (size_t)r0 * PART_STRIDE + col) =
                    make_float2(acc[mt][nt][0], acc[mt][nt][1]);
                *reinterpret_cast<float2*>(pb + (size_t)(r0 + 8) * PART_STRIDE + col) =
                    make_float2(acc[mt][nt][2], acc[mt][nt][3]);
            }
        }
    }
    asm volatile("bar.sync 1, 512;" ::: "memory");

    if (kgroup == 0) {
        const float2* b2 = reinterpret_cast<const float2*>(bias);
        int row0 = m0 + cwid * 32 + g;
#pragma unroll
        for (int mt = 0; mt < 2; mt++) {
            int rloc = cwid * 32 + mt * 16 + g;
            int r = row0 + mt * 16;
#pragma unroll
            for (int nt = 0; nt < 8; nt++) {
                int col = nt * 8 + 2 * t;
                float2 bv = b2[col >> 1];
                float s0x = acc[mt][nt][0], s0y = acc[mt][nt][1];
                float s1x = acc[mt][nt][2], s1y = acc[mt][nt][3];
#pragma unroll
                for (int kg = 0; kg < 3; kg++) {
                    const float* pb = part + (size_t)kg * PART_ELEMS;
                    float2 p0 = *reinterpret_cast<const float2*>(pb + (size_t)rloc * PART_STRIDE + col);
                    float2 p1 = *reinterpret_cast<const float2*>(pb + (size_t)(rloc + 8) * PART_STRIDE + col);
                    s0x += p0.x; s0y += p0.y;
                    s1x += p1.x; s1y += p1.y;
                }
                *reinterpret_cast<float2*>(out + (size_t)r * OUT_F + col) =
                    make_float2(s0x + bv.x, s0y + bv.y);
                *reinterpret_cast<float2*>(out + (size_t)(r + 8) * OUT_F + col) =
                    make_float2(s1x + bv.x, s1y + bv.y);
            }
        }
    }
}

// ---------------------------------------------------------------- host
typedef CUresult (*tmap_encode_fn)(
    CUtensorMap*, CUtensorMapDataType, cuuint32_t, void*,
    const cuuint64_t*, const cuuint64_t*, const cuuint32_t*, const cuuint32_t*,
    CUtensorMapInterleave, CUtensorMapSwizzle, CUtensorMapL2promotion,
    CUtensorMapFloatOOBfill);

extern "C" void kernel_launch(void* const* d_in, const int* in_sizes, int n_in,
                              void* d_out, int out_size) {
    const float* x    = (const float*)d_in[0];
    const float* adj  = (const float*)d_in[1];
    const float* w    = (const float*)d_in[2];
    const float* bias = (const float*)d_in[3];
    float* out = (float*)d_out;

    void* supT_ptr = nullptr;
    cudaGetSymbolAddress(&supT_ptr, g_supT);
    float* supT = (float*)supT_ptr;

    gcn_support_kernel<<<K_DIM / 64, 256>>>(x, w, supT);

    // Driver entry point via cudart (no -lcuda link dependency)
    tmap_encode_fn enc = nullptr;
    cudaDriverEntryPointQueryResult qr;
    cudaGetDriverEntryPointByVersion("cuTensorMapEncodeTiled", (void**)&enc, 12000,
                                     cudaEnableDefault, &qr);

    CUtensorMap madj{}, msup{};
    {
        cuuint64_t dims[2]    = {(cuuint64_t)K_DIM, (cuuint64_t)N_ROWS};
        cuuint64_t strides[1] = {(cuuint64_t)K_DIM * sizeof(float)};
        cuuint32_t box[2]     = {TILE_K, TILE_M};   // 128B x 128 rows, SW128
        cuuint32_t es[2]      = {1, 1};
        enc(&madj, CU_TENSOR_MAP_DATA_TYPE_FLOAT32, 2, (void*)adj,
            dims, strides, box, es,
            CU_TENSOR_MAP_INTERLEAVE_NONE, CU_TENSOR_MAP_SWIZZLE_128B,
            CU_TENSOR_MAP_L2_PROMOTION_L2_128B, CU_TENSOR_MAP_FLOAT_OOB_FILL_NONE);
    }
    {
        cuuint64_t dims[2]    = {(cuuint64_t)K_DIM, (cuuint64_t)OUT_F};
        cuuint64_t strides[1] = {(cuuint64_t)K_DIM * sizeof(float)};
        cuuint32_t box[2]     = {TILE_K, OUT_F};    // 128B x 64 rows, SW128
        cuuint32_t es[2]      = {1, 1};
        enc(&msup, CU_TENSOR_MAP_DATA_TYPE_FLOAT32, 2, (void*)supT,
            dims, strides, box, es,
            CU_TENSOR_MAP_INTERLEAVE_NONE, CU_TENSOR_MAP_SWIZZLE_128B,
            CU_TENSOR_MAP_L2_PROMOTION_L2_128B, CU_TENSOR_MAP_FLOAT_OOB_FILL_NONE);
    }

    cudaFuncSetAttribute(gcn_gemm_kernel, cudaFuncAttributeMaxDynamicSharedMemorySize,
                         SMEM_BYTES);
    gcn_gemm_kernel<<<N_ROWS / TILE_M, 544, SMEM_BYTES>>>(madj, msup, out, bias);
}

// round 6
// speedup vs baseline: 1.0711x; 1.0711x over previous
#include <cuda_runtime.h>
#include <cuda.h>
#include <cstdint>

// ============================================================================
// GraphConvolution: out = adj[16384,16384] @ (x[16384,64] @ W[64,64]) + bias
//
// Round 6: TILE_K=64, STAGES=4 (same smem). 16 compute warps (4/SMSP),
// kgroup kg owns k8-slabs {kg, kg+4} of each 64-wide k-tile. Halves the
// mbarrier poll + loop-ALU overhead per unit work (round-5 regression was
// alu 28.5%: replicated per-iteration overhead, TRYWAIT ~90cyc fast path).
// ============================================================================

#define N_ROWS 16384
#define K_DIM  16384
#define IN_F   64
#define OUT_F  64

#define TILE_M 128
#define TILE_K 64                       // two 32-col SW128 regions per operand
#define STAGES 4
#define N_ITERS (K_DIM / TILE_K)        // 256

#define A_REG_BYTES (TILE_M * 128)      // 16384 (one 32-col region)
#define B_REG_BYTES (OUT_F * 128)       // 8192
#define OFF_A0 0
#define OFF_A1 16384
#define OFF_B0 32768
#define OFF_B1 40960
#define STAGE_BYTES 49152

#define OFF_BARS  0                     // per stage: full @ 16*s, empty @ 16*s+8
#define OFF_TILES 1024
#define SMEM_BYTES (OFF_TILES + STAGES * STAGE_BYTES)   // 197632

#define N_CWARPS 16
#define PART_STRIDE 66                  // padded row stride (floats)
#define PART_ELEMS (TILE_M * PART_STRIDE)

// ---------------------------------------------------------------- PTX helpers
__device__ __forceinline__ uint32_t smem_to_u32(const void* p) {
    uint32_t a;
    asm("{ .reg .u64 t; cvta.to.shared.u64 t, %1; cvt.u32.u64 %0, t; }" : "=r"(a) : "l"(p));
    return a;
}

#define MBARRIER_INIT(addr, count) \
    asm volatile("mbarrier.init.shared.b64 [%0], %1;" :: "r"((uint32_t)(addr)), "r"((uint32_t)(count)) : "memory")

#define MBARRIER_ARRIVE(addr) \
    asm volatile("mbarrier.arrive.shared.b64 _, [%0];" :: "r"((uint32_t)(addr)) : "memory")

#define MBARRIER_EXPECT_TX(addr, bytes) \
    asm volatile("mbarrier.arrive.expect_tx.shared.b64 _, [%0], %1;" :: "r"((uint32_t)(addr)), "r"((uint32_t)(bytes)) : "memory")

#define MBARRIER_WAIT_PARITY(addr, parity) do {                                      \
    uint32_t _mbar = (uint32_t)(addr);                                               \
    uint32_t _par  = (uint32_t)(parity);                                             \
    uint32_t _done;                                                                  \
    asm volatile(                                                                    \
        "{\n\t.reg .pred p;\n\t"                                                     \
        "mbarrier.try_wait.parity.acquire.cta.shared::cta.b64 p, [%1], %2;\n\t"      \
        "selp.b32 %0, 1, 0, p;\n\t}"                                                 \
        : "=r"(_done) : "r"(_mbar), "r"(_par) : "memory");                           \
    if (!_done) {                                                                    \
        asm volatile(                                                                \
            "{\n\t.reg .pred P1;\n\t"                                                \
            "WAIT_LOOP_%=:\n\t"                                                      \
            "mbarrier.try_wait.parity.acquire.cta.shared::cta.b64 P1, [%0], %1, 0x989680;\n\t" \
            "@P1 bra.uni WAIT_DONE_%=;\n\t"                                          \
            "bra.uni WAIT_LOOP_%=;\n\t"                                              \
            "WAIT_DONE_%=:\n\t}"                                                     \
            :: "r"(_mbar), "r"(_par) : "memory");                                    \
    }                                                                                \
} while (0)

__device__ __forceinline__ void tma_load_2d_g(uint32_t smem_addr, const CUtensorMap* map,
                                              int cx, int cy, uint32_t mbar) {
    asm volatile(
        "cp.async.bulk.tensor.2d.shared::cta.global.tile.mbarrier::complete_tx::bytes "
        "[%0], [%1, {%2, %3}], [%4];"
        :: "r"(smem_addr), "l"(map), "r"(cx), "r"(cy), "r"(mbar) : "memory");
}

__device__ __forceinline__ uint32_t lds32(uint32_t a) {
    uint32_t v;
    asm volatile("ld.shared.b32 %0, [%1];" : "=r"(v) : "r"(a));
    return v;
}

__device__ __forceinline__ uint32_t f2tf32(uint32_t bits) {
    uint32_t o;
    asm("cvt.rna.tf32.f32 %0, %1;" : "=r"(o) : "f"(__uint_as_float(bits)));
    return o;
}

__device__ __forceinline__ void mma_tf32(float* c,
                                         uint32_t a0, uint32_t a1, uint32_t a2, uint32_t a3,
                                         uint32_t b0, uint32_t b1) {
    asm volatile(
        "mma.sync.aligned.m16n8k8.row.col.f32.tf32.tf32.f32 "
        "{%0,%1,%2,%3}, {%4,%5,%6,%7}, {%8,%9}, {%0,%1,%2,%3};"
        : "+f"(c[0]), "+f"(c[1]), "+f"(c[2]), "+f"(c[3])
        : "r"(a0), "r"(a1), "r"(a2), "r"(a3), "r"(b0), "r"(b1));
}

// ---------------------------------------------------------------- scratch
__device__ __align__(1024) float g_supT[(size_t)OUT_F * K_DIM];  // 4 MiB

// ---------------------------------------------------------------- kernel 1
__global__ void __launch_bounds__(256) gcn_support_kernel(const float* __restrict__ x,
                                                          const float* __restrict__ w,
                                                          float* __restrict__ supT) {
    __shared__ float ws[IN_F * OUT_F];
    int tid = threadIdx.x;
    for (int i = tid; i < IN_F * OUT_F; i += 256) ws[i] = w[i];
    __syncthreads();

    int k  = blockIdx.x * 64 + (tid & 63);
    int n0 = (tid >> 6) * (OUT_F / 4);

    float xr[IN_F];
    const float4* xv = reinterpret_cast<const float4*>(x + (size_t)k * IN_F);
#pragma unroll
    for (int i = 0; i < IN_F / 4; i++) {
        float4 v = xv[i];
        xr[4 * i] = v.x; xr[4 * i + 1] = v.y; xr[4 * i + 2] = v.z; xr[4 * i + 3] = v.w;
    }
#pragma unroll 4
    for (int nn = 0; nn < OUT_F / 4; nn++) {
        int n = n0 + nn;
        float acc = 0.f;
#pragma unroll
        for (int i = 0; i < IN_F; i++) acc = fmaf(xr[i], ws[i * OUT_F + n], acc);
        uint32_t t;
        asm("cvt.rna.tf32.f32 %0, %1;" : "=r"(t) : "f"(acc));  // pre-round to tf32
        supT[(size_t)n * K_DIM + k] = __uint_as_float(t);
    }
}

// ---------------------------------------------------------------- kernel 2
// 17 warps: wid 0..15 compute (4 row groups x 4 k-groups), wid 16 = producer.
__global__ void __launch_bounds__(544, 1) gcn_gemm_kernel(
    const __grid_constant__ CUtensorMap madj,
    const __grid_constant__ CUtensorMap msup,
    float* __restrict__ out,
    const float* __restrict__ bias)
{
    extern __shared__ char smem[];
    uint32_t sb = smem_to_u32(smem);
    int tid = threadIdx.x;
    int wid = tid >> 5;
    int lid = tid & 31;
    int m0 = blockIdx.x * TILE_M;

    if (tid == 0) {
        for (int s = 0; s < STAGES; s++) {
            MBARRIER_INIT(sb + OFF_BARS + s * 16, 1);            // full: 1 expect_tx
            MBARRIER_INIT(sb + OFF_BARS + s * 16 + 8, N_CWARPS); // empty: 16 arrives
        }
    }
    __syncthreads();

    if (wid == 16) {
        if (lid == 0) {
            // -------- producer: 4 TMA loads per stage (A lo/hi, B lo/hi)
            int s = 0; uint32_t ph = 1;  // flipped phase: first STAGES waits pass
            for (int it = 0; it < N_ITERS; it++) {
                uint32_t fb = sb + OFF_BARS + s * 16;
                MBARRIER_WAIT_PARITY(fb + 8, ph);
                MBARRIER_EXPECT_TX(fb, STAGE_BYTES);
                uint32_t st = sb + OFF_TILES + s * STAGE_BYTES;
                int k0 = it * TILE_K;
                tma_load_2d_g(st + OFF_A0, &madj, k0,      m0, fb);
                tma_load_2d_g(st + OFF_A1, &madj, k0 + 32, m0, fb);
                tma_load_2d_g(st + OFF_B0, &msup, k0,      0,  fb);
                tma_load_2d_g(st + OFF_B1, &msup, k0 + 32, 0,  fb);
                if (++s == STAGES) { s = 0; ph ^= 1; }
            }
        }
        return;
    }

    // -------- compute warps
    int cwid   = wid & 3;      // row group: rows [32*cwid, 32*cwid+32)
    int kgroup = wid >> 2;     // owns k8-slab kgroup in region0 and region1
    int g = lid >> 2;          // 0..7
    int t = lid & 3;           // 0..3
    uint32_t xorv = (uint32_t)g << 4;   // SW128 swizzle term (rows used == g mod 8)

    uint32_t rA0 = (uint32_t)(cwid * 32 + g) * 128;   // mt0 upper 8 rows
    uint32_t rB[8];
#pragma unroll
    for (int nt = 0; nt < 8; nt++) rB[nt] = (uint32_t)(nt * 8 + g) * 128;

    float acc[2][8][4];
#pragma unroll
    for (int mt = 0; mt < 2; mt++)
#pragma unroll
        for (int nt = 0; nt < 8; nt++)
#pragma unroll
            for (int c = 0; c < 4; c++) acc[mt][nt][c] = 0.f;

    // column byte offsets within a 32-col region for this warp's k8 slab
    uint32_t cb0 = ((uint32_t)(kgroup * 32 + t * 4)) ^ xorv;        // k = t
    uint32_t cb1 = ((uint32_t)(kgroup * 32 + t * 4 + 16)) ^ xorv;   // k = t+4

    int s = 0; uint32_t ph = 0;
    for (int it = 0; it < N_ITERS; it++) {
        uint32_t fb = sb + OFF_BARS + s * 16;
        MBARRIER_WAIT_PARITY(fb, ph);
        uint32_t st = sb + OFF_TILES + s * STAGE_BYTES;

#pragma unroll
        for (int kk = 0; kk < 2; kk++) {
            uint32_t sA = st + (kk ? OFF_A1 : OFF_A0);
            uint32_t sB = st + (kk ? OFF_B1 : OFF_B0);

            uint32_t a00 = f2tf32(lds32(sA + rA0 + cb0));
            uint32_t a01 = f2tf32(lds32(sA + rA0 + 1024 + cb0));
            uint32_t a02 = f2tf32(lds32(sA + rA0 + cb1));
            uint32_t a03 = f2tf32(lds32(sA + rA0 + 1024 + cb1));
            uint32_t a10 = f2tf32(lds32(sA + rA0 + 2048 + cb0));
            uint32_t a11 = f2tf32(lds32(sA + rA0 + 3072 + cb0));
            uint32_t a12 = f2tf32(lds32(sA + rA0 + 2048 + cb1));
            uint32_t a13 = f2tf32(lds32(sA + rA0 + 3072 + cb1));

#pragma unroll
            for (int nt = 0; nt < 8; nt++) {
                uint32_t b0 = lds32(sB + rB[nt] + cb0);
                uint32_t b1 = lds32(sB + rB[nt] + cb1);
                mma_tf32(acc[0][nt], a00, a01, a02, a03, b0, b1);
                mma_tf32(acc[1][nt], a10, a11, a12, a13, b0, b1);
            }
        }
        if (lid == 0) MBARRIER_ARRIVE(fb + 8);
        if (++s == STAGES) { s = 0; ph ^= 1; }
    }

    // -------- drain barrier: all compute warps must finish reading tile smem
    // before it is reused for partials (producer is provably done too).
    asm volatile("bar.sync 1, 512;" ::: "memory");

    // -------- reduction: kgroups 1..3 write partials to smem, kgroup 0 sums
    float* part = reinterpret_cast<float*>(smem + OFF_TILES);
    if (kgroup != 0) {
        float* pb = part + (size_t)(kgroup - 1) * PART_ELEMS;
#pragma unroll
        for (int mt = 0; mt < 2; mt++) {
            int r0 = cwid * 32 + mt * 16 + g;
#pragma unroll
            for (int nt = 0; nt < 8; nt++) {
                int col = nt * 8 + 2 * t;
                *reinterpret_cast<float2*>(pb + (size_t)r0 * PART_STRIDE + col) =
                    make_float2(acc[mt][nt][0], acc[mt][nt][1]);
                *reinterpret_cast<float2*>(pb + (size_t)(r0 + 8) * PART_STRIDE + col) =
                    make_float2(acc[mt][nt][2], acc[mt][nt][3]);
            }
        }
    }
    asm volatile("bar.sync 1, 512;" ::: "memory");

    if (kgroup == 0) {
        const float2* b2 = reinterpret_cast<const float2*>(bias);
        int row0 = m0 + cwid * 32 + g;
#pragma unroll
        for (int mt = 0; mt < 2; mt++) {
            int rloc = cwid * 32 + mt * 16 + g;
            int r = row0 + mt * 16;
#pragma unroll
            for (int nt = 0; nt < 8; nt++) {
                int col = nt * 8 + 2 * t;
                float2 bv = b2[col >> 1];
                float s0x = acc[mt][nt][0], s0y = acc[mt][nt][1];
                float s1x = acc[mt][nt][2], s1y = acc[mt][nt][3];
#pragma unroll
                for (int kg = 0; kg < 3; kg++) {
                    const float* pb = part + (size_t)kg * PART_ELEMS;
                    float2 p0 = *reinterpret_cast<const float2*>(pb + (size_t)rloc * PART_STRIDE + col);
                    float2 p1 = *reinterpret_cast<const float2*>(pb + (size_t)(rloc + 8) * PART_STRIDE + col);
                    s0x += p0.x; s0y += p0.y;
                    s1x += p1.x; s1y += p1.y;
                }
                *reinterpret_cast<float2*>(out + (size_t)r * OUT_F + col) =
                    make_float2(s0x + bv.x, s0y + bv.y);
                *reinterpret_cast<float2*>(out + (size_t)(r + 8) * OUT_F + col) =
                    make_float2(s1x + bv.x, s1y + bv.y);
            }
        }
    }
}

// ---------------------------------------------------------------- host
typedef CUresult (*tmap_encode_fn)(
    CUtensorMap*, CUtensorMapDataType, cuuint32_t, void*,
    const cuuint64_t*, const cuuint64_t*, const cuuint32_t*, const cuuint32_t*,
    CUtensorMapInterleave, CUtensorMapSwizzle, CUtensorMapL2promotion,
    CUtensorMapFloatOOBfill);

extern "C" void kernel_launch(void* const* d_in, const int* in_sizes, int n_in,
                              void* d_out, int out_size) {
    const float* x    = (const float*)d_in[0];
    const float* adj  = (const float*)d_in[1];
    const float* w    = (const float*)d_in[2];
    const float* bias = (const float*)d_in[3];
    float* out = (float*)d_out;

    void* supT_ptr = nullptr;
    cudaGetSymbolAddress(&supT_ptr, g_supT);
    float* supT = (float*)supT_ptr;

    gcn_support_kernel<<<K_DIM / 64, 256>>>(x, w, supT);

    // Driver entry point via cudart (no -lcuda link dependency)
    tmap_encode_fn enc = nullptr;
    cudaDriverEntryPointQueryResult qr;
    cudaGetDriverEntryPointByVersion("cuTensorMapEncodeTiled", (void**)&enc, 12000,
                                     cudaEnableDefault, &qr);

    CUtensorMap madj{}, msup{};
    {
        cuuint64_t dims[2]    = {(cuuint64_t)K_DIM, (cuuint64_t)N_ROWS};
        cuuint64_t strides[1] = {(cuuint64_t)K_DIM * sizeof(float)};
        cuuint32_t box[2]     = {32, TILE_M};       // 128B x 128 rows, SW128
        cuuint32_t es[2]      = {1, 1};
        enc(&madj, CU_TENSOR_MAP_DATA_TYPE_FLOAT32, 2, (void*)adj,
            dims, strides, box, es,
            CU_TENSOR_MAP_INTERLEAVE_NONE, CU_TENSOR_MAP_SWIZZLE_128B,
            CU_TENSOR_MAP_L2_PROMOTION_L2_128B, CU_TENSOR_MAP_FLOAT_OOB_FILL_NONE);
    }
    {
        cuuint64_t dims[2]    = {(cuuint64_t)K_DIM, (cuuint64_t)OUT_F};
        cuuint64_t strides[1] = {(cuuint64_t)K_DIM * sizeof(float)};
        cuuint32_t box[2]     = {32, OUT_F};        // 128B x 64 rows, SW128
        cuuint32_t es[2]      = {1, 1};
        enc(&msup, CU_TENSOR_MAP_DATA_TYPE_FLOAT32, 2, (void*)supT,
            dims, strides, box, es,
            CU_TENSOR_MAP_INTERLEAVE_NONE, CU_TENSOR_MAP_SWIZZLE_128B,
            CU_TENSOR_MAP_L2_PROMOTION_L2_128B, CU_TENSOR_MAP_FLOAT_OOB_FILL_NONE);
    }

    cudaFuncSetAttribute(gcn_gemm_kernel, cudaFuncAttributeMaxDynamicSharedMemorySize,
                         SMEM_BYTES);
    gcn_gemm_kernel<<<N_ROWS / TILE_M, 544, SMEM_BYTES>>>(madj, msup, out, bias);
}